// round 1
// baseline (speedup 1.0000x reference)
#include <cuda_runtime.h>
#include <math.h>

// Problem dims (fixed by the reference)
constexpr int B_   = 64;
constexpr int S_   = 512;
constexpr int D_   = 256;
constexpr int H_   = 8;
constexpr int DK_  = 32;
constexpr int DFF_ = 1024;
constexpr int BS_  = B_ * S_;          // 32768 rows
constexpr float SCALE_ = 0.17677669529663687f; // 1/sqrt(32)

// ---------------------------------------------------------------------------
// Scratch (no allocations allowed -> __device__ globals)
// ---------------------------------------------------------------------------
__device__ float g_y  [BS_ * D_];
__device__ float g_x  [BS_ * D_];
__device__ float g_kp [BS_ * D_];
__device__ float g_vp [BS_ * D_];
__device__ float g_att[BS_ * D_];
__device__ float g_o  [BS_ * D_];
__device__ float g_x1 [BS_ * D_];
__device__ float g_f  [BS_ * D_];
__device__ float g_h  [BS_ * DFF_];

// ---------------------------------------------------------------------------
// SGEMM: C[M,N] = A[M,K] @ W[K,N] + bias[N], optional ReLU. fp32.
// 128x128 block tile, BK=8, 256 threads, 8x8 per-thread microtile.
// M,N divisible by 128; K divisible by 8 (true for all our shapes).
// ---------------------------------------------------------------------------
__global__ __launch_bounds__(256) void sgemm_bias(
    const float* __restrict__ A, const float* __restrict__ W,
    const float* __restrict__ bias, float* __restrict__ C,
    int M, int N, int K, int relu)
{
    __shared__ float As[8][128];
    __shared__ float Bs[8][128];

    const int tid = threadIdx.x;
    const int bx = blockIdx.x, by = blockIdx.y;

    // A tile loader: 128 rows x 8 cols, one float4 per thread
    const int arow = tid >> 1;
    const int acol = (tid & 1) << 2;
    // B tile loader: 8 rows x 128 cols, one float4 per thread
    const int brow = tid >> 5;
    const int bcol = (tid & 31) << 2;

    const int ty = (tid >> 4) << 3;   // microtile row offset
    const int tx = (tid & 15) << 3;   // microtile col offset

    const float* Ap = A + (size_t)(by * 128) * K;
    const float* Wp = W + bx * 128;

    float acc[8][8];
    #pragma unroll
    for (int i = 0; i < 8; i++)
        #pragma unroll
        for (int j = 0; j < 8; j++) acc[i][j] = 0.f;

    for (int k0 = 0; k0 < K; k0 += 8) {
        float4 av = *(const float4*)(Ap + (size_t)arow * K + k0 + acol);
        float4 bv = *(const float4*)(Wp + (size_t)(k0 + brow) * N + bcol);
        As[acol + 0][arow] = av.x;
        As[acol + 1][arow] = av.y;
        As[acol + 2][arow] = av.z;
        As[acol + 3][arow] = av.w;
        *(float4*)&Bs[brow][bcol] = bv;
        __syncthreads();

        #pragma unroll
        for (int kk = 0; kk < 8; kk++) {
            float a[8], b[8];
            *(float4*)(a)     = *(float4*)&As[kk][ty];
            *(float4*)(a + 4) = *(float4*)&As[kk][ty + 4];
            *(float4*)(b)     = *(float4*)&Bs[kk][tx];
            *(float4*)(b + 4) = *(float4*)&Bs[kk][tx + 4];
            #pragma unroll
            for (int i = 0; i < 8; i++)
                #pragma unroll
                for (int j = 0; j < 8; j++)
                    acc[i][j] += a[i] * b[j];
        }
        __syncthreads();
    }

    const int colb = bx * 128 + tx;
    #pragma unroll
    for (int i = 0; i < 8; i++) {
        const int row = by * 128 + ty + i;
        #pragma unroll
        for (int j = 0; j < 8; j++) {
            float v = acc[i][j] + bias[colb + j];
            if (relu) v = fmaxf(v, 0.f);
            acc[i][j] = v;
        }
        *(float4*)&C[(size_t)row * N + colb]     = *(float4*)&acc[i][0];
        *(float4*)&C[(size_t)row * N + colb + 4] = *(float4*)&acc[i][4];
    }
}

// ---------------------------------------------------------------------------
// Fused causal attention (flash-style). q and k share the same projection
// (kq_same in the reference). One block = one (b,h) pair x 64 q-rows.
// strict=0: allow k<=q ; strict=1: allow k<q (row 0 fully masked -> output 0,
// matching the reference's softmax(...)*mask semantics).
// ---------------------------------------------------------------------------
__global__ __launch_bounds__(256) void attn_kernel(
    const float* __restrict__ QK, const float* __restrict__ Vp,
    float* __restrict__ O, int strict)
{
    const int qt = blockIdx.x;         // q tile (0..7)
    const int bh = blockIdx.y;         // 0..511
    const int b  = bh >> 3;
    const int h  = bh & 7;
    const int q0 = qt << 6;
    const int t  = threadIdx.x;

    __shared__ float Qs[64][33];       // padded (scalar reads)
    __shared__ float Kts[32][68];      // K transposed: [dk][krow], padded
    __shared__ float Vs[64][32];       // float4-friendly
    __shared__ float Ss[64][65];       // scores / probs, padded

    const size_t base = (size_t)(b * S_) * D_ + h * DK_;

    // Load Q tile (64 x 32)
    for (int i = t; i < 512; i += 256) {
        const int r = i >> 3, c = (i & 7) << 2;
        float4 v = *(const float4*)&QK[base + (size_t)(q0 + r) * D_ + c];
        Qs[r][c] = v.x; Qs[r][c + 1] = v.y; Qs[r][c + 2] = v.z; Qs[r][c + 3] = v.w;
    }

    const int r       = t >> 2;        // owned q row (0..63)
    const int quarter = t & 3;
    const int pc0     = quarter << 4;  // prob col range (16 wide)
    const int vc0     = quarter << 3;  // out col range (8 wide)
    const int qg      = (t >> 4) << 2; // score rows (4)
    const int kg      = (t & 15) << 2; // score cols (4)

    float acc[8];
    #pragma unroll
    for (int c = 0; c < 8; c++) acc[c] = 0.f;
    float m = -1e30f, l = 0.f;

    for (int kt = 0; kt <= qt; kt++) {
        const int k0 = kt << 6;
        __syncthreads();   // previous iter done reading Ss/Vs; Q load fencing below
        for (int i = t; i < 512; i += 256) {
            const int rr = i >> 3, c = (i & 7) << 2;
            float4 kv4 = *(const float4*)&QK[base + (size_t)(k0 + rr) * D_ + c];
            Kts[c][rr] = kv4.x; Kts[c + 1][rr] = kv4.y;
            Kts[c + 2][rr] = kv4.z; Kts[c + 3][rr] = kv4.w;
            *(float4*)&Vs[rr][c] = *(const float4*)&Vp[base + (size_t)(k0 + rr) * D_ + c];
        }
        __syncthreads();

        // 4x4 score microtile per thread
        float sc[4][4];
        #pragma unroll
        for (int i = 0; i < 4; i++)
            #pragma unroll
            for (int j = 0; j < 4; j++) sc[i][j] = 0.f;
        #pragma unroll
        for (int kk = 0; kk < 32; kk++) {
            float qv[4], kv[4];
            #pragma unroll
            for (int i = 0; i < 4; i++) { qv[i] = Qs[qg + i][kk]; kv[i] = Kts[kk][kg + i]; }
            #pragma unroll
            for (int i = 0; i < 4; i++)
                #pragma unroll
                for (int j = 0; j < 4; j++)
                    sc[i][j] += qv[i] * kv[j];
        }
        #pragma unroll
        for (int i = 0; i < 4; i++)
            #pragma unroll
            for (int j = 0; j < 4; j++) {
                const int gq = q0 + qg + i, gk = k0 + kg + j;
                Ss[qg + i][kg + j] = (gk <= gq - strict) ? sc[i][j] * SCALE_ : -1e30f;
            }
        __syncthreads();

        // Online softmax: 4 threads per row, 16 cols each
        float tm = -1e30f;
        #pragma unroll
        for (int j = 0; j < 16; j++) tm = fmaxf(tm, Ss[r][pc0 + j]);
        tm = fmaxf(tm, __shfl_xor_sync(0xffffffffu, tm, 1));
        tm = fmaxf(tm, __shfl_xor_sync(0xffffffffu, tm, 2));
        const float nm = fmaxf(m, tm);
        const float corr = __expf(m - nm);
        float ps = 0.f;
        #pragma unroll
        for (int j = 0; j < 16; j++) {
            const float sv = Ss[r][pc0 + j];
            const float p = (sv > -1e29f) ? __expf(sv - nm) : 0.f;  // masked -> exactly 0
            Ss[r][pc0 + j] = p;
            ps += p;
        }
        ps += __shfl_xor_sync(0xffffffffu, ps, 1);
        ps += __shfl_xor_sync(0xffffffffu, ps, 2);
        l = l * corr + ps;
        m = nm;
        #pragma unroll
        for (int c = 0; c < 8; c++) acc[c] *= corr;
        __syncthreads();

        // acc += P @ V (thread owns 1 row x 8 cols)
        #pragma unroll 8
        for (int k = 0; k < 64; k++) {
            const float p = Ss[r][k];
            float4 va = *(float4*)&Vs[k][vc0];
            float4 vb = *(float4*)&Vs[k][vc0 + 4];
            acc[0] += p * va.x; acc[1] += p * va.y; acc[2] += p * va.z; acc[3] += p * va.w;
            acc[4] += p * vb.x; acc[5] += p * vb.y; acc[6] += p * vb.z; acc[7] += p * vb.w;
        }
    }

    const float inv = (l > 0.f) ? 1.f / l : 0.f;   // fully-masked row -> 0
    float4 oa = make_float4(acc[0] * inv, acc[1] * inv, acc[2] * inv, acc[3] * inv);
    float4 ob = make_float4(acc[4] * inv, acc[5] * inv, acc[6] * inv, acc[7] * inv);
    *(float4*)&O[base + (size_t)(q0 + r) * D_ + vc0]     = oa;
    *(float4*)&O[base + (size_t)(q0 + r) * D_ + vc0 + 4] = ob;
}

// ---------------------------------------------------------------------------
// Fused residual add + LayerNorm (two-pass variance, matching the reference)
// One block per row, 256 threads = D elements.
// ---------------------------------------------------------------------------
__global__ __launch_bounds__(256) void add_ln_kernel(
    const float* __restrict__ X, const float* __restrict__ R,
    const float* __restrict__ gam, const float* __restrict__ bet,
    float* __restrict__ O)
{
    const int row = blockIdx.x;
    const int t = threadIdx.x;
    const size_t idx = (size_t)row * D_ + t;
    const float v = X[idx] + R[idx];

    __shared__ float red[8];
    float s = v;
    #pragma unroll
    for (int o = 16; o > 0; o >>= 1) s += __shfl_xor_sync(0xffffffffu, s, o);
    if ((t & 31) == 0) red[t >> 5] = s;
    __syncthreads();
    float tot = 0.f;
    #pragma unroll
    for (int i = 0; i < 8; i++) tot += red[i];
    const float mu = tot * (1.f / 256.f);

    const float d = v - mu;
    __syncthreads();   // red reuse
    float s2 = d * d;
    #pragma unroll
    for (int o = 16; o > 0; o >>= 1) s2 += __shfl_xor_sync(0xffffffffu, s2, o);
    if ((t & 31) == 0) red[t >> 5] = s2;
    __syncthreads();
    float tot2 = 0.f;
    #pragma unroll
    for (int i = 0; i < 8; i++) tot2 += red[i];
    const float var = tot2 * (1.f / 256.f);

    O[idx] = d * rsqrtf(var + 1e-5f) * gam[t] + bet[t];
}

// ---------------------------------------------------------------------------
// Host-side orchestration
// ---------------------------------------------------------------------------
struct Scratch { float *y, *x, *kp, *vp, *att, *o, *x1, *f, *h; };

static void launch_layer(const float* Qin, const float* Vin, float* Out,
                         int li, int strict, int apply_pos,
                         void* const* d_in, const Scratch& P)
{
    const float* Wk  = (const float*)d_in[2]  + (size_t)li * D_ * D_;
    const float* bk  = (const float*)d_in[3]  + (size_t)li * D_;
    const float* Wv  = (const float*)d_in[4]  + (size_t)li * D_ * D_;
    const float* bv  = (const float*)d_in[5]  + (size_t)li * D_;
    const float* Wo  = (const float*)d_in[6]  + (size_t)li * D_ * D_;
    const float* bo  = (const float*)d_in[7]  + (size_t)li * D_;
    const float* g1  = (const float*)d_in[8]  + (size_t)li * D_;
    const float* be1 = (const float*)d_in[9]  + (size_t)li * D_;
    const float* W1  = (const float*)d_in[10] + (size_t)li * D_ * DFF_;
    const float* bf1 = (const float*)d_in[11] + (size_t)li * DFF_;
    const float* W2  = (const float*)d_in[12] + (size_t)li * DFF_ * D_;
    const float* bf2 = (const float*)d_in[13] + (size_t)li * D_;
    const float* g2  = (const float*)d_in[14] + (size_t)li * D_;
    const float* be2 = (const float*)d_in[15] + (size_t)li * D_;

    const dim3 gp(D_ / 128, BS_ / 128);   // (2, 256)

    // q==k projection (kq_same): one GEMM serves both
    sgemm_bias<<<gp, 256>>>(Qin, Wk, bk, P.kp, BS_, D_, D_, 0);
    sgemm_bias<<<gp, 256>>>(Vin, Wv, bv, P.vp, BS_, D_, D_, 0);
    attn_kernel<<<dim3(S_ / 64, B_ * H_), 256>>>(P.kp, P.vp, P.att, strict);
    sgemm_bias<<<gp, 256>>>(P.att, Wo, bo, P.o, BS_, D_, D_, 0);

    float* ln1out = apply_pos ? P.x1 : Out;
    add_ln_kernel<<<BS_, 256>>>(Qin, P.o, g1, be1, ln1out);

    if (apply_pos) {
        sgemm_bias<<<dim3(DFF_ / 128, BS_ / 128), 256>>>(P.x1, W1, bf1, P.h, BS_, DFF_, D_, 1);
        sgemm_bias<<<dim3(D_ / 128, BS_ / 128), 256>>>(P.h, W2, bf2, P.f, BS_, D_, DFF_, 0);
        add_ln_kernel<<<BS_, 256>>>(P.x1, P.f, g2, be2, Out);
    }
}

extern "C" void kernel_launch(void* const* d_in, const int* in_sizes, int n_in,
                              void* d_out, int out_size)
{
    (void)in_sizes; (void)n_in; (void)out_size;
    const float* qe = (const float*)d_in[0];   // q_embed_data  -> x stream
    const float* qa = (const float*)d_in[1];   // qa_embed_data -> y stream

    Scratch P;
    cudaGetSymbolAddress((void**)&P.y,  g_y);
    cudaGetSymbolAddress((void**)&P.x,  g_x);
    cudaGetSymbolAddress((void**)&P.kp, g_kp);
    cudaGetSymbolAddress((void**)&P.vp, g_vp);
    cudaGetSymbolAddress((void**)&P.att, g_att);
    cudaGetSymbolAddress((void**)&P.o,  g_o);
    cudaGetSymbolAddress((void**)&P.x1, g_x1);
    cudaGetSymbolAddress((void**)&P.f,  g_f);
    cudaGetSymbolAddress((void**)&P.h,  g_h);

    // Encoder blocks (y = qa stream), mask incl. diagonal, with FFN
    launch_layer(qa,  qa,  P.y, 0, /*strict=*/0, /*apply_pos=*/1, d_in, P);
    launch_layer(P.y, P.y, P.y, 1, 0, 1, d_in, P);

    // Decoder blocks on x stream
    launch_layer(qe,  qe,  P.x, 2, /*strict=*/0, /*apply_pos=*/0, d_in, P);   // self, no FFN
    launch_layer(P.x, P.y, P.x, 3, /*strict=*/1, /*apply_pos=*/1, d_in, P);   // cross (V=y)
    launch_layer(P.x, P.x, P.x, 4, 0, 0, d_in, P);                            // self, no FFN
    launch_layer(P.x, P.y, (float*)d_out, 5, 1, 1, d_in, P);                  // cross -> out
}

// round 2
// speedup vs baseline: 1.6134x; 1.6134x over previous
#include <cuda_runtime.h>
#include <math.h>

// Problem dims (fixed by the reference)
constexpr int B_   = 64;
constexpr int S_   = 512;
constexpr int D_   = 256;
constexpr int H_   = 8;
constexpr int DK_  = 32;
constexpr int DFF_ = 1024;
constexpr int BS_  = B_ * S_;          // 32768 rows
constexpr float SCALE_ = 0.17677669529663687f; // 1/sqrt(32)

// ---------------------------------------------------------------------------
// Scratch (no allocations allowed -> __device__ globals)
// ---------------------------------------------------------------------------
__device__ float g_y  [BS_ * D_];
__device__ float g_x  [BS_ * D_];
__device__ float g_kp [BS_ * D_];
__device__ float g_vp [BS_ * D_];
__device__ float g_att[BS_ * D_];
__device__ float g_o  [BS_ * D_];
__device__ float g_x1 [BS_ * D_];
__device__ float g_f  [BS_ * D_];
__device__ float g_h  [BS_ * DFF_];

// ---------------------------------------------------------------------------
// tf32 helpers
// ---------------------------------------------------------------------------
__device__ __forceinline__ float f2tf32(float x) {
    unsigned r;
    asm("cvt.rna.tf32.f32 %0, %1;" : "=r"(r) : "f"(x));
    return __uint_as_float(r);
}

__device__ __forceinline__ void mma_tf32(
    float& c0, float& c1, float& c2, float& c3,
    unsigned a0, unsigned a1, unsigned a2, unsigned a3,
    unsigned b0, unsigned b1)
{
    asm volatile(
        "mma.sync.aligned.m16n8k8.row.col.f32.tf32.tf32.f32 "
        "{%0,%1,%2,%3}, {%4,%5,%6,%7}, {%8,%9}, {%0,%1,%2,%3};\n"
        : "+f"(c0), "+f"(c1), "+f"(c2), "+f"(c3)
        : "r"(a0), "r"(a1), "r"(a2), "r"(a3), "r"(b0), "r"(b1));
}

// ---------------------------------------------------------------------------
// Tensor-core GEMM (tf32): C[M,N] = A[M,K] @ W[K,N] + bias[N], optional ReLU.
// Block tile 128x128, BK=16, 256 threads = 8 warps, each warp 64x32.
// Warp does m16n8k8 mma: 4 m-tiles x 4 n-tiles per k8 step.
// As layout [m][k] pad 20 floats/row  -> conflict-free A-frag loads.
// Bs layout [k][n] pad 136 floats/row -> conflict-free B-frag loads.
// M,N div 128; K div 16 (all our shapes).
// ---------------------------------------------------------------------------
constexpr int APAD = 20;    // 16 + 4
constexpr int BPAD = 136;   // 128 + 8

__global__ __launch_bounds__(256) void gemm_tc(
    const float* __restrict__ A, const float* __restrict__ W,
    const float* __restrict__ bias, float* __restrict__ C,
    int M, int N, int K, int relu)
{
    __shared__ float As[128 * APAD];
    __shared__ float Bs[16 * BPAD];

    const int tid  = threadIdx.x;
    const int lane = tid & 31;
    const int warp = tid >> 5;
    const int wm   = warp >> 2;          // 0..1  -> m offset wm*64
    const int wn   = warp & 3;           // 0..3  -> n offset wn*32
    const int g    = lane >> 2;          // fragment row group
    const int t4   = lane & 3;           // fragment k/col lane
    const int mrow = wm * 64;
    const int nb   = wn * 32;

    const int bm = blockIdx.y * 128;
    const int bn = blockIdx.x * 128;

    float acc[4][4][4];
    #pragma unroll
    for (int mt = 0; mt < 4; mt++)
        #pragma unroll
        for (int nt = 0; nt < 4; nt++)
            #pragma unroll
            for (int i = 0; i < 4; i++) acc[mt][nt][i] = 0.f;

    for (int k0 = 0; k0 < K; k0 += 16) {
        // ---- stage A: 128x16, transposed access (thread: 2 float4 along k)
        #pragma unroll
        for (int i = 0; i < 2; i++) {
            const int f  = tid + (i << 8);       // 0..511
            const int m  = f >> 2;               // 0..127
            const int kq = (f & 3) << 2;         // 0,4,8,12
            const float4 v = *(const float4*)&A[(size_t)(bm + m) * K + k0 + kq];
            float4 w;
            w.x = f2tf32(v.x); w.y = f2tf32(v.y);
            w.z = f2tf32(v.z); w.w = f2tf32(v.w);
            *(float4*)&As[m * APAD + kq] = w;
        }
        // ---- stage B: 16x128 (thread: 2 float4 along n)
        #pragma unroll
        for (int i = 0; i < 2; i++) {
            const int f  = tid + (i << 8);
            const int kk = f >> 5;               // 0..15
            const int n  = (f & 31) << 2;        // 0..124
            const float4 v = *(const float4*)&W[(size_t)(k0 + kk) * N + bn + n];
            float4 w;
            w.x = f2tf32(v.x); w.y = f2tf32(v.y);
            w.z = f2tf32(v.z); w.w = f2tf32(v.w);
            *(float4*)&Bs[kk * BPAD + n] = w;
        }
        __syncthreads();

        #pragma unroll
        for (int ks = 0; ks < 16; ks += 8) {
            unsigned a[4][4], b[4][2];
            #pragma unroll
            for (int mt = 0; mt < 4; mt++) {
                const float* Ap = &As[(mrow + mt * 16 + g) * APAD + ks + t4];
                a[mt][0] = __float_as_uint(Ap[0]);
                a[mt][1] = __float_as_uint(Ap[8 * APAD]);
                a[mt][2] = __float_as_uint(Ap[4]);
                a[mt][3] = __float_as_uint(Ap[8 * APAD + 4]);
            }
            #pragma unroll
            for (int nt = 0; nt < 4; nt++) {
                const float* Bp = &Bs[(ks + t4) * BPAD + nb + nt * 8 + g];
                b[nt][0] = __float_as_uint(Bp[0]);
                b[nt][1] = __float_as_uint(Bp[4 * BPAD]);
            }
            #pragma unroll
            for (int mt = 0; mt < 4; mt++)
                #pragma unroll
                for (int nt = 0; nt < 4; nt++)
                    mma_tf32(acc[mt][nt][0], acc[mt][nt][1],
                             acc[mt][nt][2], acc[mt][nt][3],
                             a[mt][0], a[mt][1], a[mt][2], a[mt][3],
                             b[nt][0], b[nt][1]);
        }
        __syncthreads();
    }

    // ---- epilogue: bias (+ReLU), write float2 pairs
    #pragma unroll
    for (int mt = 0; mt < 4; mt++) {
        const int r = bm + mrow + mt * 16 + g;
        #pragma unroll
        for (int nt = 0; nt < 4; nt++) {
            const int c = bn + nb + nt * 8 + 2 * t4;
            const float b0 = bias[c], b1 = bias[c + 1];
            float v0 = acc[mt][nt][0] + b0;
            float v1 = acc[mt][nt][1] + b1;
            float v2 = acc[mt][nt][2] + b0;
            float v3 = acc[mt][nt][3] + b1;
            if (relu) {
                v0 = fmaxf(v0, 0.f); v1 = fmaxf(v1, 0.f);
                v2 = fmaxf(v2, 0.f); v3 = fmaxf(v3, 0.f);
            }
            *(float2*)&C[(size_t)r * N + c]       = make_float2(v0, v1);
            *(float2*)&C[(size_t)(r + 8) * N + c] = make_float2(v2, v3);
        }
    }
}

// ---------------------------------------------------------------------------
// Fused causal attention (flash-style, SIMT fp32). q and k share projection.
// One block = one (b,h) pair x 64 q-rows.
// strict=0: allow k<=q ; strict=1: allow k<q (fully-masked row -> 0).
// ---------------------------------------------------------------------------
__global__ __launch_bounds__(256) void attn_kernel(
    const float* __restrict__ QK, const float* __restrict__ Vp,
    float* __restrict__ O, int strict)
{
    const int qt = blockIdx.x;         // q tile (0..7)
    const int bh = blockIdx.y;         // 0..511
    const int b  = bh >> 3;
    const int h  = bh & 7;
    const int q0 = qt << 6;
    const int t  = threadIdx.x;

    __shared__ float Qs[64][33];
    __shared__ float Kts[32][68];
    __shared__ float Vs[64][32];
    __shared__ float Ss[64][65];

    const size_t base = (size_t)(b * S_) * D_ + h * DK_;

    for (int i = t; i < 512; i += 256) {
        const int r = i >> 3, c = (i & 7) << 2;
        float4 v = *(const float4*)&QK[base + (size_t)(q0 + r) * D_ + c];
        Qs[r][c] = v.x; Qs[r][c + 1] = v.y; Qs[r][c + 2] = v.z; Qs[r][c + 3] = v.w;
    }

    const int r       = t >> 2;
    const int quarter = t & 3;
    const int pc0     = quarter << 4;
    const int vc0     = quarter << 3;
    const int qg      = (t >> 4) << 2;
    const int kg      = (t & 15) << 2;

    float acc[8];
    #pragma unroll
    for (int c = 0; c < 8; c++) acc[c] = 0.f;
    float m = -1e30f, l = 0.f;

    for (int kt = 0; kt <= qt; kt++) {
        const int k0 = kt << 6;
        __syncthreads();
        for (int i = t; i < 512; i += 256) {
            const int rr = i >> 3, c = (i & 7) << 2;
            float4 kv4 = *(const float4*)&QK[base + (size_t)(k0 + rr) * D_ + c];
            Kts[c][rr] = kv4.x; Kts[c + 1][rr] = kv4.y;
            Kts[c + 2][rr] = kv4.z; Kts[c + 3][rr] = kv4.w;
            *(float4*)&Vs[rr][c] = *(const float4*)&Vp[base + (size_t)(k0 + rr) * D_ + c];
        }
        __syncthreads();

        float sc[4][4];
        #pragma unroll
        for (int i = 0; i < 4; i++)
            #pragma unroll
            for (int j = 0; j < 4; j++) sc[i][j] = 0.f;
        #pragma unroll
        for (int kk = 0; kk < 32; kk++) {
            float qv[4], kv[4];
            #pragma unroll
            for (int i = 0; i < 4; i++) { qv[i] = Qs[qg + i][kk]; kv[i] = Kts[kk][kg + i]; }
            #pragma unroll
            for (int i = 0; i < 4; i++)
                #pragma unroll
                for (int j = 0; j < 4; j++)
                    sc[i][j] += qv[i] * kv[j];
        }
        #pragma unroll
        for (int i = 0; i < 4; i++)
            #pragma unroll
            for (int j = 0; j < 4; j++) {
                const int gq = q0 + qg + i, gk = k0 + kg + j;
                Ss[qg + i][kg + j] = (gk <= gq - strict) ? sc[i][j] * SCALE_ : -1e30f;
            }
        __syncthreads();

        float tm = -1e30f;
        #pragma unroll
        for (int j = 0; j < 16; j++) tm = fmaxf(tm, Ss[r][pc0 + j]);
        tm = fmaxf(tm, __shfl_xor_sync(0xffffffffu, tm, 1));
        tm = fmaxf(tm, __shfl_xor_sync(0xffffffffu, tm, 2));
        const float nm = fmaxf(m, tm);
        const float corr = __expf(m - nm);
        float ps = 0.f;
        #pragma unroll
        for (int j = 0; j < 16; j++) {
            const float sv = Ss[r][pc0 + j];
            const float p = (sv > -1e29f) ? __expf(sv - nm) : 0.f;
            Ss[r][pc0 + j] = p;
            ps += p;
        }
        ps += __shfl_xor_sync(0xffffffffu, ps, 1);
        ps += __shfl_xor_sync(0xffffffffu, ps, 2);
        l = l * corr + ps;
        m = nm;
        #pragma unroll
        for (int c = 0; c < 8; c++) acc[c] *= corr;
        __syncthreads();

        #pragma unroll 8
        for (int k = 0; k < 64; k++) {
            const float p = Ss[r][k];
            float4 va = *(float4*)&Vs[k][vc0];
            float4 vb = *(float4*)&Vs[k][vc0 + 4];
            acc[0] += p * va.x; acc[1] += p * va.y; acc[2] += p * va.z; acc[3] += p * va.w;
            acc[4] += p * vb.x; acc[5] += p * vb.y; acc[6] += p * vb.z; acc[7] += p * vb.w;
        }
    }

    const float inv = (l > 0.f) ? 1.f / l : 0.f;
    float4 oa = make_float4(acc[0] * inv, acc[1] * inv, acc[2] * inv, acc[3] * inv);
    float4 ob = make_float4(acc[4] * inv, acc[5] * inv, acc[6] * inv, acc[7] * inv);
    *(float4*)&O[base + (size_t)(q0 + r) * D_ + vc0]     = oa;
    *(float4*)&O[base + (size_t)(q0 + r) * D_ + vc0 + 4] = ob;
}

// ---------------------------------------------------------------------------
// Fused residual add + LayerNorm (two-pass variance, matching the reference)
// ---------------------------------------------------------------------------
__global__ __launch_bounds__(256) void add_ln_kernel(
    const float* __restrict__ X, const float* __restrict__ R,
    const float* __restrict__ gam, const float* __restrict__ bet,
    float* __restrict__ O)
{
    const int row = blockIdx.x;
    const int t = threadIdx.x;
    const size_t idx = (size_t)row * D_ + t;
    const float v = X[idx] + R[idx];

    __shared__ float red[8];
    float s = v;
    #pragma unroll
    for (int o = 16; o > 0; o >>= 1) s += __shfl_xor_sync(0xffffffffu, s, o);
    if ((t & 31) == 0) red[t >> 5] = s;
    __syncthreads();
    float tot = 0.f;
    #pragma unroll
    for (int i = 0; i < 8; i++) tot += red[i];
    const float mu = tot * (1.f / 256.f);

    const float d = v - mu;
    __syncthreads();
    float s2 = d * d;
    #pragma unroll
    for (int o = 16; o > 0; o >>= 1) s2 += __shfl_xor_sync(0xffffffffu, s2, o);
    if ((t & 31) == 0) red[t >> 5] = s2;
    __syncthreads();
    float tot2 = 0.f;
    #pragma unroll
    for (int i = 0; i < 8; i++) tot2 += red[i];
    const float var = tot2 * (1.f / 256.f);

    O[idx] = d * rsqrtf(var + 1e-5f) * gam[t] + bet[t];
}

// ---------------------------------------------------------------------------
// Host-side orchestration
// ---------------------------------------------------------------------------
struct Scratch { float *y, *x, *kp, *vp, *att, *o, *x1, *f, *h; };

static void launch_layer(const float* Qin, const float* Vin, float* Out,
                         int li, int strict, int apply_pos,
                         void* const* d_in, const Scratch& P)
{
    const float* Wk  = (const float*)d_in[2]  + (size_t)li * D_ * D_;
    const float* bk  = (const float*)d_in[3]  + (size_t)li * D_;
    const float* Wv  = (const float*)d_in[4]  + (size_t)li * D_ * D_;
    const float* bv  = (const float*)d_in[5]  + (size_t)li * D_;
    const float* Wo  = (const float*)d_in[6]  + (size_t)li * D_ * D_;
    const float* bo  = (const float*)d_in[7]  + (size_t)li * D_;
    const float* g1  = (const float*)d_in[8]  + (size_t)li * D_;
    const float* be1 = (const float*)d_in[9]  + (size_t)li * D_;
    const float* W1  = (const float*)d_in[10] + (size_t)li * D_ * DFF_;
    const float* bf1 = (const float*)d_in[11] + (size_t)li * DFF_;
    const float* W2  = (const float*)d_in[12] + (size_t)li * DFF_ * D_;
    const float* bf2 = (const float*)d_in[13] + (size_t)li * D_;
    const float* g2  = (const float*)d_in[14] + (size_t)li * D_;
    const float* be2 = (const float*)d_in[15] + (size_t)li * D_;

    const dim3 gp(D_ / 128, BS_ / 128);   // (2, 256)

    // q==k projection (kq_same): one GEMM serves both
    gemm_tc<<<gp, 256>>>(Qin, Wk, bk, P.kp, BS_, D_, D_, 0);
    gemm_tc<<<gp, 256>>>(Vin, Wv, bv, P.vp, BS_, D_, D_, 0);
    attn_kernel<<<dim3(S_ / 64, B_ * H_), 256>>>(P.kp, P.vp, P.att, strict);
    gemm_tc<<<gp, 256>>>(P.att, Wo, bo, P.o, BS_, D_, D_, 0);

    float* ln1out = apply_pos ? P.x1 : Out;
    add_ln_kernel<<<BS_, 256>>>(Qin, P.o, g1, be1, ln1out);

    if (apply_pos) {
        gemm_tc<<<dim3(DFF_ / 128, BS_ / 128), 256>>>(P.x1, W1, bf1, P.h, BS_, DFF_, D_, 1);
        gemm_tc<<<dim3(D_ / 128, BS_ / 128), 256>>>(P.h, W2, bf2, P.f, BS_, D_, DFF_, 0);
        add_ln_kernel<<<BS_, 256>>>(P.x1, P.f, g2, be2, Out);
    }
}

extern "C" void kernel_launch(void* const* d_in, const int* in_sizes, int n_in,
                              void* d_out, int out_size)
{
    (void)in_sizes; (void)n_in; (void)out_size;
    const float* qe = (const float*)d_in[0];   // q_embed_data  -> x stream
    const float* qa = (const float*)d_in[1];   // qa_embed_data -> y stream

    Scratch P;
    cudaGetSymbolAddress((void**)&P.y,  g_y);
    cudaGetSymbolAddress((void**)&P.x,  g_x);
    cudaGetSymbolAddress((void**)&P.kp, g_kp);
    cudaGetSymbolAddress((void**)&P.vp, g_vp);
    cudaGetSymbolAddress((void**)&P.att, g_att);
    cudaGetSymbolAddress((void**)&P.o,  g_o);
    cudaGetSymbolAddress((void**)&P.x1, g_x1);
    cudaGetSymbolAddress((void**)&P.f,  g_f);
    cudaGetSymbolAddress((void**)&P.h,  g_h);

    // Encoder blocks (y = qa stream), mask incl. diagonal, with FFN
    launch_layer(qa,  qa,  P.y, 0, /*strict=*/0, /*apply_pos=*/1, d_in, P);
    launch_layer(P.y, P.y, P.y, 1, 0, 1, d_in, P);

    // Decoder blocks on x stream
    launch_layer(qe,  qe,  P.x, 2, /*strict=*/0, /*apply_pos=*/0, d_in, P);   // self, no FFN
    launch_layer(P.x, P.y, P.x, 3, /*strict=*/1, /*apply_pos=*/1, d_in, P);   // cross (V=y)
    launch_layer(P.x, P.x, P.x, 4, 0, 0, d_in, P);                            // self, no FFN
    launch_layer(P.x, P.y, (float*)d_out, 5, 1, 1, d_in, P);                  // cross -> out
}

// round 3
// speedup vs baseline: 2.0745x; 1.2858x over previous
#include <cuda_runtime.h>
#include <math.h>

// Problem dims (fixed by the reference)
constexpr int B_   = 64;
constexpr int S_   = 512;
constexpr int D_   = 256;
constexpr int H_   = 8;
constexpr int DK_  = 32;
constexpr int DFF_ = 1024;
constexpr int BS_  = B_ * S_;          // 32768 rows
constexpr float SCALE_ = 0.17677669529663687f; // 1/sqrt(32)

// ---------------------------------------------------------------------------
// Scratch (no allocations allowed -> __device__ globals)
// ---------------------------------------------------------------------------
__device__ float g_y  [BS_ * D_];
__device__ float g_x  [BS_ * D_];
__device__ float g_kp [BS_ * D_];
__device__ float g_vp [BS_ * D_];
__device__ float g_att[BS_ * D_];
__device__ float g_o  [BS_ * D_];
__device__ float g_x1 [BS_ * D_];
__device__ float g_f  [BS_ * D_];
__device__ float g_h  [BS_ * DFF_];

// ---------------------------------------------------------------------------
// tf32 helpers
// ---------------------------------------------------------------------------
__device__ __forceinline__ float f2tf32(float x) {
    unsigned r;
    asm("cvt.rna.tf32.f32 %0, %1;" : "=r"(r) : "f"(x));
    return __uint_as_float(r);
}

__device__ __forceinline__ void mma_tf32(
    float& c0, float& c1, float& c2, float& c3,
    unsigned a0, unsigned a1, unsigned a2, unsigned a3,
    unsigned b0, unsigned b1)
{
    asm volatile(
        "mma.sync.aligned.m16n8k8.row.col.f32.tf32.tf32.f32 "
        "{%0,%1,%2,%3}, {%4,%5,%6,%7}, {%8,%9}, {%0,%1,%2,%3};\n"
        : "+f"(c0), "+f"(c1), "+f"(c2), "+f"(c3)
        : "r"(a0), "r"(a1), "r"(a2), "r"(a3), "r"(b0), "r"(b1));
}

// ---------------------------------------------------------------------------
// Tensor-core GEMM (tf32), double-buffered: C = A @ W + bias, optional ReLU.
// Block tile 128x128, BK=16, 256 threads = 8 warps, warp tile 64x32.
// Prefetch next K-tile to registers BEFORE the mma loop; cvt+STS after.
// ---------------------------------------------------------------------------
constexpr int APAD = 20;    // 16 + 4
constexpr int BPAD = 136;   // 128 + 8
constexpr int ASZ  = 128 * APAD;
constexpr int BSZ  = 16 * BPAD;

__global__ __launch_bounds__(256, 2) void gemm_tc(
    const float* __restrict__ A, const float* __restrict__ W,
    const float* __restrict__ bias, float* __restrict__ C,
    int M, int N, int K, int relu)
{
    __shared__ float As[2 * ASZ];
    __shared__ float Bs[2 * BSZ];

    const int tid  = threadIdx.x;
    const int lane = tid & 31;
    const int warp = tid >> 5;
    const int wm   = warp >> 2;
    const int wn   = warp & 3;
    const int g    = lane >> 2;
    const int t4   = lane & 3;
    const int mrow = wm * 64;
    const int nb   = wn * 32;

    const int bm = blockIdx.y * 128;
    const int bn = blockIdx.x * 128;
    const int nk = K >> 4;

    float acc[4][4][4];
    #pragma unroll
    for (int mt = 0; mt < 4; mt++)
        #pragma unroll
        for (int nt = 0; nt < 4; nt++)
            #pragma unroll
            for (int i = 0; i < 4; i++) acc[mt][nt][i] = 0.f;

    // stage K-tile 0 into buffer 0
    {
        #pragma unroll
        for (int i = 0; i < 2; i++) {
            const int f  = tid + (i << 8);
            const int m  = f >> 2;
            const int kq = (f & 3) << 2;
            const float4 v = *(const float4*)&A[(size_t)(bm + m) * K + kq];
            As[m * APAD + kq + 0] = f2tf32(v.x);
            As[m * APAD + kq + 1] = f2tf32(v.y);
            As[m * APAD + kq + 2] = f2tf32(v.z);
            As[m * APAD + kq + 3] = f2tf32(v.w);
            const int kk = f >> 5;
            const int n  = (f & 31) << 2;
            const float4 w = *(const float4*)&W[(size_t)kk * N + bn + n];
            Bs[kk * BPAD + n + 0] = f2tf32(w.x);
            Bs[kk * BPAD + n + 1] = f2tf32(w.y);
            Bs[kk * BPAD + n + 2] = f2tf32(w.z);
            Bs[kk * BPAD + n + 3] = f2tf32(w.w);
        }
    }
    __syncthreads();

    for (int kt = 0; kt < nk; kt++) {
        const int cur = kt & 1;
        const bool pf = (kt + 1 < nk);
        float4 av[2], bv[2];
        if (pf) {
            const int k0n = (kt + 1) << 4;
            #pragma unroll
            for (int i = 0; i < 2; i++) {
                const int f = tid + (i << 8);
                av[i] = *(const float4*)&A[(size_t)(bm + (f >> 2)) * K + k0n + ((f & 3) << 2)];
                bv[i] = *(const float4*)&W[(size_t)(k0n + (f >> 5)) * N + bn + ((f & 31) << 2)];
            }
        }

        const float* Asc = As + cur * ASZ;
        const float* Bsc = Bs + cur * BSZ;
        #pragma unroll
        for (int ks = 0; ks < 16; ks += 8) {
            unsigned a[4][4], b[4][2];
            #pragma unroll
            for (int mt = 0; mt < 4; mt++) {
                const float* Ap = &Asc[(mrow + mt * 16 + g) * APAD + ks + t4];
                a[mt][0] = __float_as_uint(Ap[0]);
                a[mt][1] = __float_as_uint(Ap[8 * APAD]);
                a[mt][2] = __float_as_uint(Ap[4]);
                a[mt][3] = __float_as_uint(Ap[8 * APAD + 4]);
            }
            #pragma unroll
            for (int nt = 0; nt < 4; nt++) {
                const float* Bp = &Bsc[(ks + t4) * BPAD + nb + nt * 8 + g];
                b[nt][0] = __float_as_uint(Bp[0]);
                b[nt][1] = __float_as_uint(Bp[4 * BPAD]);
            }
            #pragma unroll
            for (int mt = 0; mt < 4; mt++)
                #pragma unroll
                for (int nt = 0; nt < 4; nt++)
                    mma_tf32(acc[mt][nt][0], acc[mt][nt][1],
                             acc[mt][nt][2], acc[mt][nt][3],
                             a[mt][0], a[mt][1], a[mt][2], a[mt][3],
                             b[nt][0], b[nt][1]);
        }

        if (pf) {
            float* Asn = As + (cur ^ 1) * ASZ;
            float* Bsn = Bs + (cur ^ 1) * BSZ;
            #pragma unroll
            for (int i = 0; i < 2; i++) {
                const int f  = tid + (i << 8);
                const int m  = f >> 2;
                const int kq = (f & 3) << 2;
                Asn[m * APAD + kq + 0] = f2tf32(av[i].x);
                Asn[m * APAD + kq + 1] = f2tf32(av[i].y);
                Asn[m * APAD + kq + 2] = f2tf32(av[i].z);
                Asn[m * APAD + kq + 3] = f2tf32(av[i].w);
                const int kk = f >> 5;
                const int n  = (f & 31) << 2;
                Bsn[kk * BPAD + n + 0] = f2tf32(bv[i].x);
                Bsn[kk * BPAD + n + 1] = f2tf32(bv[i].y);
                Bsn[kk * BPAD + n + 2] = f2tf32(bv[i].z);
                Bsn[kk * BPAD + n + 3] = f2tf32(bv[i].w);
            }
        }
        __syncthreads();
    }

    // epilogue: bias (+ReLU)
    #pragma unroll
    for (int mt = 0; mt < 4; mt++) {
        const int r = bm + mrow + mt * 16 + g;
        #pragma unroll
        for (int nt = 0; nt < 4; nt++) {
            const int c = bn + nb + nt * 8 + 2 * t4;
            const float b0 = bias[c], b1 = bias[c + 1];
            float v0 = acc[mt][nt][0] + b0;
            float v1 = acc[mt][nt][1] + b1;
            float v2 = acc[mt][nt][2] + b0;
            float v3 = acc[mt][nt][3] + b1;
            if (relu) {
                v0 = fmaxf(v0, 0.f); v1 = fmaxf(v1, 0.f);
                v2 = fmaxf(v2, 0.f); v3 = fmaxf(v3, 0.f);
            }
            *(float2*)&C[(size_t)r * N + c]       = make_float2(v0, v1);
            *(float2*)&C[(size_t)(r + 8) * N + c] = make_float2(v2, v3);
        }
    }
}

// ---------------------------------------------------------------------------
// Tensor-core flash attention (tf32 mma for QK^T and PV; softmax SIMT fp32).
// One block = (b,h) x 64 q-rows. kv-tiles of 64. q==k projection shared.
// Warp layout: m0=(warp>>1)*16; scores n=(warp&1)*32 wide 32; PV n=(warp&1)*16.
// ---------------------------------------------------------------------------
__global__ __launch_bounds__(256) void attn_tc(
    const float* __restrict__ QK, const float* __restrict__ Vp,
    float* __restrict__ O, int strict)
{
    const int qt = blockIdx.x;
    const int bh = blockIdx.y;
    const int b  = bh >> 3;
    const int h  = bh & 7;
    const int q0 = qt << 6;
    const int t  = threadIdx.x;
    const int lane = t & 31;
    const int warp = t >> 5;
    const int m0   = (warp >> 1) << 4;
    const int n0s  = (warp & 1) << 5;   // score cols base (0/32)
    const int n0o  = (warp & 1) << 4;   // output cols base (0/16)
    const int g    = lane >> 2;
    const int t4   = lane & 3;

    __shared__ float Qs[64][33];
    __shared__ float Ks[64][33];
    __shared__ float Vs[64][33];
    __shared__ float Ss[64][72];
    __shared__ float rowtmp[64];

    const size_t base = (size_t)(b * S_) * D_ + h * DK_;

    // load + convert Q tile (64 x 32)
    for (int i = t; i < 512; i += 256) {
        const int r = i >> 3, c = (i & 7) << 2;
        float4 v = *(const float4*)&QK[base + (size_t)(q0 + r) * D_ + c];
        Qs[r][c + 0] = f2tf32(v.x); Qs[r][c + 1] = f2tf32(v.y);
        Qs[r][c + 2] = f2tf32(v.z); Qs[r][c + 3] = f2tf32(v.w);
    }

    float acc_o[2][4];
    #pragma unroll
    for (int nt = 0; nt < 2; nt++)
        #pragma unroll
        for (int i = 0; i < 4; i++) acc_o[nt][i] = 0.f;

    // softmax role: thread handles row sr, 16 cols starting pc0
    const int sr  = t >> 2;
    const int qtr = t & 3;
    const int pc0 = qtr << 4;
    float m = -1e30f, l = 0.f;

    for (int kt = 0; kt <= qt; kt++) {
        const int k0 = kt << 6;
        __syncthreads();   // Ss/Ks/Vs free from previous iteration; Qs visible
        for (int i = t; i < 512; i += 256) {
            const int rr = i >> 3, c = (i & 7) << 2;
            float4 kv = *(const float4*)&QK[base + (size_t)(k0 + rr) * D_ + c];
            Ks[rr][c + 0] = f2tf32(kv.x); Ks[rr][c + 1] = f2tf32(kv.y);
            Ks[rr][c + 2] = f2tf32(kv.z); Ks[rr][c + 3] = f2tf32(kv.w);
            float4 vv = *(const float4*)&Vp[base + (size_t)(k0 + rr) * D_ + c];
            Vs[rr][c + 0] = f2tf32(vv.x); Vs[rr][c + 1] = f2tf32(vv.y);
            Vs[rr][c + 2] = f2tf32(vv.z); Vs[rr][c + 3] = f2tf32(vv.w);
        }
        __syncthreads();

        // ---- scores: S[64x64] = Q @ K^T (warp tile 16x32)
        float acc_s[4][4];
        #pragma unroll
        for (int nt = 0; nt < 4; nt++)
            #pragma unroll
            for (int i = 0; i < 4; i++) acc_s[nt][i] = 0.f;

        #pragma unroll
        for (int ks = 0; ks < 32; ks += 8) {
            unsigned a0 = __float_as_uint(Qs[m0 + g][ks + t4]);
            unsigned a1 = __float_as_uint(Qs[m0 + g + 8][ks + t4]);
            unsigned a2 = __float_as_uint(Qs[m0 + g][ks + t4 + 4]);
            unsigned a3 = __float_as_uint(Qs[m0 + g + 8][ks + t4 + 4]);
            #pragma unroll
            for (int nt = 0; nt < 4; nt++) {
                unsigned b0 = __float_as_uint(Ks[n0s + nt * 8 + g][ks + t4]);
                unsigned b1 = __float_as_uint(Ks[n0s + nt * 8 + g][ks + t4 + 4]);
                mma_tf32(acc_s[nt][0], acc_s[nt][1], acc_s[nt][2], acc_s[nt][3],
                         a0, a1, a2, a3, b0, b1);
            }
        }
        // mask + scale -> Ss
        #pragma unroll
        for (int nt = 0; nt < 4; nt++) {
            const int cl  = n0s + nt * 8 + 2 * t4;
            const int gqa = q0 + m0 + g;
            const int gqb = gqa + 8;
            const int gk0 = k0 + cl, gk1 = gk0 + 1;
            Ss[m0 + g][cl]         = (gk0 <= gqa - strict) ? acc_s[nt][0] * SCALE_ : -1e30f;
            Ss[m0 + g][cl + 1]     = (gk1 <= gqa - strict) ? acc_s[nt][1] * SCALE_ : -1e30f;
            Ss[m0 + g + 8][cl]     = (gk0 <= gqb - strict) ? acc_s[nt][2] * SCALE_ : -1e30f;
            Ss[m0 + g + 8][cl + 1] = (gk1 <= gqb - strict) ? acc_s[nt][3] * SCALE_ : -1e30f;
        }
        __syncthreads();

        // ---- online softmax (fp32, 4 threads per row x 16 cols)
        float tm = -1e30f;
        #pragma unroll
        for (int j = 0; j < 16; j++) tm = fmaxf(tm, Ss[sr][pc0 + j]);
        tm = fmaxf(tm, __shfl_xor_sync(0xffffffffu, tm, 1));
        tm = fmaxf(tm, __shfl_xor_sync(0xffffffffu, tm, 2));
        const float nm   = fmaxf(m, tm);
        const float corr = __expf(m - nm);
        float ps = 0.f;
        #pragma unroll
        for (int j = 0; j < 16; j++) {
            const float sv = Ss[sr][pc0 + j];
            const float p  = (sv > -1e29f) ? __expf(sv - nm) : 0.f;
            const float pt = f2tf32(p);
            Ss[sr][pc0 + j] = pt;
            ps += pt;
        }
        ps += __shfl_xor_sync(0xffffffffu, ps, 1);
        ps += __shfl_xor_sync(0xffffffffu, ps, 2);
        l = l * corr + ps;
        m = nm;
        if (qtr == 0) rowtmp[sr] = corr;
        __syncthreads();

        // ---- PV: acc_o = acc_o * corr + P @ V (warp tile 16x16)
        const float ca = rowtmp[m0 + g];
        const float cb = rowtmp[m0 + g + 8];
        #pragma unroll
        for (int nt = 0; nt < 2; nt++) {
            acc_o[nt][0] *= ca; acc_o[nt][1] *= ca;
            acc_o[nt][2] *= cb; acc_o[nt][3] *= cb;
        }
        #pragma unroll
        for (int kk = 0; kk < 64; kk += 8) {
            unsigned a0 = __float_as_uint(Ss[m0 + g][kk + t4]);
            unsigned a1 = __float_as_uint(Ss[m0 + g + 8][kk + t4]);
            unsigned a2 = __float_as_uint(Ss[m0 + g][kk + t4 + 4]);
            unsigned a3 = __float_as_uint(Ss[m0 + g + 8][kk + t4 + 4]);
            #pragma unroll
            for (int nt = 0; nt < 2; nt++) {
                unsigned b0 = __float_as_uint(Vs[kk + t4][n0o + nt * 8 + g]);
                unsigned b1 = __float_as_uint(Vs[kk + t4 + 4][n0o + nt * 8 + g]);
                mma_tf32(acc_o[nt][0], acc_o[nt][1], acc_o[nt][2], acc_o[nt][3],
                         a0, a1, a2, a3, b0, b1);
            }
        }
    }

    // finalize: divide by l (fully-masked row -> 0), write out
    __syncthreads();
    if (qtr == 0) rowtmp[sr] = (l > 0.f) ? 1.f / l : 0.f;
    __syncthreads();
    const float ia = rowtmp[m0 + g];
    const float ib = rowtmp[m0 + g + 8];
    #pragma unroll
    for (int nt = 0; nt < 2; nt++) {
        const int c   = n0o + nt * 8 + 2 * t4;
        const int gqa = q0 + m0 + g;
        *(float2*)&O[base + (size_t)gqa * D_ + c] =
            make_float2(acc_o[nt][0] * ia, acc_o[nt][1] * ia);
        *(float2*)&O[base + (size_t)(gqa + 8) * D_ + c] =
            make_float2(acc_o[nt][2] * ib, acc_o[nt][3] * ib);
    }
}

// ---------------------------------------------------------------------------
// Fused residual add + LayerNorm: warp-per-row (256 floats, 8 per lane).
// ---------------------------------------------------------------------------
__global__ __launch_bounds__(256) void add_ln_kernel(
    const float* __restrict__ X, const float* __restrict__ R,
    const float* __restrict__ gam, const float* __restrict__ bet,
    float* __restrict__ O)
{
    const int warp = threadIdx.x >> 5;
    const int lane = threadIdx.x & 31;
    const int row  = blockIdx.x * 8 + warp;
    const size_t off = (size_t)row * D_ + lane * 8;

    float4 x0 = *(const float4*)&X[off];
    float4 x1 = *(const float4*)&X[off + 4];
    float4 r0 = *(const float4*)&R[off];
    float4 r1 = *(const float4*)&R[off + 4];
    float v[8] = { x0.x + r0.x, x0.y + r0.y, x0.z + r0.z, x0.w + r0.w,
                   x1.x + r1.x, x1.y + r1.y, x1.z + r1.z, x1.w + r1.w };

    float s = 0.f;
    #pragma unroll
    for (int i = 0; i < 8; i++) s += v[i];
    #pragma unroll
    for (int o = 16; o > 0; o >>= 1) s += __shfl_xor_sync(0xffffffffu, s, o);
    const float mu = s * (1.f / 256.f);

    float s2 = 0.f;
    #pragma unroll
    for (int i = 0; i < 8; i++) { v[i] -= mu; s2 += v[i] * v[i]; }
    #pragma unroll
    for (int o = 16; o > 0; o >>= 1) s2 += __shfl_xor_sync(0xffffffffu, s2, o);
    const float rs = rsqrtf(s2 * (1.f / 256.f) + 1e-5f);

    const int c = lane * 8;
    float4 ga = *(const float4*)&gam[c];
    float4 gb = *(const float4*)&gam[c + 4];
    float4 ba = *(const float4*)&bet[c];
    float4 bb = *(const float4*)&bet[c + 4];

    float4 oa = make_float4(v[0] * rs * ga.x + ba.x, v[1] * rs * ga.y + ba.y,
                            v[2] * rs * ga.z + ba.z, v[3] * rs * ga.w + ba.w);
    float4 ob = make_float4(v[4] * rs * gb.x + bb.x, v[5] * rs * gb.y + bb.y,
                            v[6] * rs * gb.z + bb.z, v[7] * rs * gb.w + bb.w);
    *(float4*)&O[off]     = oa;
    *(float4*)&O[off + 4] = ob;
}

// ---------------------------------------------------------------------------
// Host-side orchestration
// ---------------------------------------------------------------------------
struct Scratch { float *y, *x, *kp, *vp, *att, *o, *x1, *f, *h; };

static void launch_layer(const float* Qin, const float* Vin, float* Out,
                         int li, int strict, int apply_pos,
                         void* const* d_in, const Scratch& P)
{
    const float* Wk  = (const float*)d_in[2]  + (size_t)li * D_ * D_;
    const float* bk  = (const float*)d_in[3]  + (size_t)li * D_;
    const float* Wv  = (const float*)d_in[4]  + (size_t)li * D_ * D_;
    const float* bv  = (const float*)d_in[5]  + (size_t)li * D_;
    const float* Wo  = (const float*)d_in[6]  + (size_t)li * D_ * D_;
    const float* bo  = (const float*)d_in[7]  + (size_t)li * D_;
    const float* g1  = (const float*)d_in[8]  + (size_t)li * D_;
    const float* be1 = (const float*)d_in[9]  + (size_t)li * D_;
    const float* W1  = (const float*)d_in[10] + (size_t)li * D_ * DFF_;
    const float* bf1 = (const float*)d_in[11] + (size_t)li * DFF_;
    const float* W2  = (const float*)d_in[12] + (size_t)li * DFF_ * D_;
    const float* bf2 = (const float*)d_in[13] + (size_t)li * D_;
    const float* g2  = (const float*)d_in[14] + (size_t)li * D_;
    const float* be2 = (const float*)d_in[15] + (size_t)li * D_;

    const dim3 gp(D_ / 128, BS_ / 128);   // (2, 256)

    // q==k projection (kq_same): one GEMM serves both
    gemm_tc<<<gp, 256>>>(Qin, Wk, bk, P.kp, BS_, D_, D_, 0);
    gemm_tc<<<gp, 256>>>(Vin, Wv, bv, P.vp, BS_, D_, D_, 0);
    attn_tc<<<dim3(S_ / 64, B_ * H_), 256>>>(P.kp, P.vp, P.att, strict);
    gemm_tc<<<gp, 256>>>(P.att, Wo, bo, P.o, BS_, D_, D_, 0);

    float* ln1out = apply_pos ? P.x1 : Out;
    add_ln_kernel<<<BS_ / 8, 256>>>(Qin, P.o, g1, be1, ln1out);

    if (apply_pos) {
        gemm_tc<<<dim3(DFF_ / 128, BS_ / 128), 256>>>(P.x1, W1, bf1, P.h, BS_, DFF_, D_, 1);
        gemm_tc<<<dim3(D_ / 128, BS_ / 128), 256>>>(P.h, W2, bf2, P.f, BS_, D_, DFF_, 0);
        add_ln_kernel<<<BS_ / 8, 256>>>(P.x1, P.f, g2, be2, Out);
    }
}

extern "C" void kernel_launch(void* const* d_in, const int* in_sizes, int n_in,
                              void* d_out, int out_size)
{
    (void)in_sizes; (void)n_in; (void)out_size;
    const float* qe = (const float*)d_in[0];   // q_embed_data  -> x stream
    const float* qa = (const float*)d_in[1];   // qa_embed_data -> y stream

    Scratch P;
    cudaGetSymbolAddress((void**)&P.y,  g_y);
    cudaGetSymbolAddress((void**)&P.x,  g_x);
    cudaGetSymbolAddress((void**)&P.kp, g_kp);
    cudaGetSymbolAddress((void**)&P.vp, g_vp);
    cudaGetSymbolAddress((void**)&P.att, g_att);
    cudaGetSymbolAddress((void**)&P.o,  g_o);
    cudaGetSymbolAddress((void**)&P.x1, g_x1);
    cudaGetSymbolAddress((void**)&P.f,  g_f);
    cudaGetSymbolAddress((void**)&P.h,  g_h);

    // Encoder blocks (y = qa stream), mask incl. diagonal, with FFN
    launch_layer(qa,  qa,  P.y, 0, /*strict=*/0, /*apply_pos=*/1, d_in, P);
    launch_layer(P.y, P.y, P.y, 1, 0, 1, d_in, P);

    // Decoder blocks on x stream
    launch_layer(qe,  qe,  P.x, 2, /*strict=*/0, /*apply_pos=*/0, d_in, P);   // self, no FFN
    launch_layer(P.x, P.y, P.x, 3, /*strict=*/1, /*apply_pos=*/1, d_in, P);   // cross (V=y)
    launch_layer(P.x, P.x, P.x, 4, 0, 0, d_in, P);                            // self, no FFN
    launch_layer(P.x, P.y, (float*)d_out, 5, 1, 1, d_in, P);                  // cross -> out
}

// round 4
// speedup vs baseline: 2.7929x; 1.3463x over previous
#include <cuda_runtime.h>
#include <math.h>

// Problem dims (fixed by the reference)
constexpr int B_   = 64;
constexpr int S_   = 512;
constexpr int D_   = 256;
constexpr int H_   = 8;
constexpr int DK_  = 32;
constexpr int DFF_ = 1024;
constexpr int BS_  = B_ * S_;          // 32768 rows
constexpr float SCALE_ = 0.17677669529663687f; // 1/sqrt(32)

// ---------------------------------------------------------------------------
// Scratch (no allocations allowed -> __device__ globals)
// ---------------------------------------------------------------------------
__device__ float g_y  [BS_ * D_];
__device__ float g_x  [BS_ * D_];
__device__ float g_kp [BS_ * D_];
__device__ float g_vp [BS_ * D_];
__device__ float g_att[BS_ * D_];
__device__ float g_o  [BS_ * D_];
__device__ float g_x1 [BS_ * D_];
__device__ float g_f  [BS_ * D_];
__device__ float g_h  [BS_ * DFF_];

// ---------------------------------------------------------------------------
// tf32 helpers
// ---------------------------------------------------------------------------
__device__ __forceinline__ float f2tf32(float x) {
    unsigned r;
    asm("cvt.rna.tf32.f32 %0, %1;" : "=r"(r) : "f"(x));
    return __uint_as_float(r);
}

__device__ __forceinline__ void mma_tf32(
    float& c0, float& c1, float& c2, float& c3,
    unsigned a0, unsigned a1, unsigned a2, unsigned a3,
    unsigned b0, unsigned b1)
{
    asm volatile(
        "mma.sync.aligned.m16n8k8.row.col.f32.tf32.tf32.f32 "
        "{%0,%1,%2,%3}, {%4,%5,%6,%7}, {%8,%9}, {%0,%1,%2,%3};\n"
        : "+f"(c0), "+f"(c1), "+f"(c2), "+f"(c3)
        : "r"(a0), "r"(a1), "r"(a2), "r"(a3), "r"(b0), "r"(b1));
}

// ---------------------------------------------------------------------------
// Tensor-core GEMM (tf32), double-buffered: C = A @ W + bias, optional ReLU.
// Block tile 128x128, BK=16, 256 threads = 8 warps, warp tile 64x32.
// ---------------------------------------------------------------------------
constexpr int APAD = 20;    // 16 + 4
constexpr int BPAD = 136;   // 128 + 8
constexpr int ASZ  = 128 * APAD;
constexpr int BSZ  = 16 * BPAD;

__global__ __launch_bounds__(256, 2) void gemm_tc(
    const float* __restrict__ A, const float* __restrict__ W,
    const float* __restrict__ bias, float* __restrict__ C,
    int M, int N, int K, int relu)
{
    __shared__ float As[2 * ASZ];
    __shared__ float Bs[2 * BSZ];

    const int tid  = threadIdx.x;
    const int lane = tid & 31;
    const int warp = tid >> 5;
    const int wm   = warp >> 2;
    const int wn   = warp & 3;
    const int g    = lane >> 2;
    const int t4   = lane & 3;
    const int mrow = wm * 64;
    const int nb   = wn * 32;

    const int bm = blockIdx.y * 128;
    const int bn = blockIdx.x * 128;
    const int nk = K >> 4;

    float acc[4][4][4];
    #pragma unroll
    for (int mt = 0; mt < 4; mt++)
        #pragma unroll
        for (int nt = 0; nt < 4; nt++)
            #pragma unroll
            for (int i = 0; i < 4; i++) acc[mt][nt][i] = 0.f;

    {
        #pragma unroll
        for (int i = 0; i < 2; i++) {
            const int f  = tid + (i << 8);
            const int m  = f >> 2;
            const int kq = (f & 3) << 2;
            const float4 v = *(const float4*)&A[(size_t)(bm + m) * K + kq];
            As[m * APAD + kq + 0] = f2tf32(v.x);
            As[m * APAD + kq + 1] = f2tf32(v.y);
            As[m * APAD + kq + 2] = f2tf32(v.z);
            As[m * APAD + kq + 3] = f2tf32(v.w);
            const int kk = f >> 5;
            const int n  = (f & 31) << 2;
            const float4 w = *(const float4*)&W[(size_t)kk * N + bn + n];
            Bs[kk * BPAD + n + 0] = f2tf32(w.x);
            Bs[kk * BPAD + n + 1] = f2tf32(w.y);
            Bs[kk * BPAD + n + 2] = f2tf32(w.z);
            Bs[kk * BPAD + n + 3] = f2tf32(w.w);
        }
    }
    __syncthreads();

    for (int kt = 0; kt < nk; kt++) {
        const int cur = kt & 1;
        const bool pf = (kt + 1 < nk);
        float4 av[2], bv[2];
        if (pf) {
            const int k0n = (kt + 1) << 4;
            #pragma unroll
            for (int i = 0; i < 2; i++) {
                const int f = tid + (i << 8);
                av[i] = *(const float4*)&A[(size_t)(bm + (f >> 2)) * K + k0n + ((f & 3) << 2)];
                bv[i] = *(const float4*)&W[(size_t)(k0n + (f >> 5)) * N + bn + ((f & 31) << 2)];
            }
        }

        const float* Asc = As + cur * ASZ;
        const float* Bsc = Bs + cur * BSZ;
        #pragma unroll
        for (int ks = 0; ks < 16; ks += 8) {
            unsigned a[4][4], b[4][2];
            #pragma unroll
            for (int mt = 0; mt < 4; mt++) {
                const float* Ap = &Asc[(mrow + mt * 16 + g) * APAD + ks + t4];
                a[mt][0] = __float_as_uint(Ap[0]);
                a[mt][1] = __float_as_uint(Ap[8 * APAD]);
                a[mt][2] = __float_as_uint(Ap[4]);
                a[mt][3] = __float_as_uint(Ap[8 * APAD + 4]);
            }
            #pragma unroll
            for (int nt = 0; nt < 4; nt++) {
                const float* Bp = &Bsc[(ks + t4) * BPAD + nb + nt * 8 + g];
                b[nt][0] = __float_as_uint(Bp[0]);
                b[nt][1] = __float_as_uint(Bp[4 * BPAD]);
            }
            #pragma unroll
            for (int mt = 0; mt < 4; mt++)
                #pragma unroll
                for (int nt = 0; nt < 4; nt++)
                    mma_tf32(acc[mt][nt][0], acc[mt][nt][1],
                             acc[mt][nt][2], acc[mt][nt][3],
                             a[mt][0], a[mt][1], a[mt][2], a[mt][3],
                             b[nt][0], b[nt][1]);
        }

        if (pf) {
            float* Asn = As + (cur ^ 1) * ASZ;
            float* Bsn = Bs + (cur ^ 1) * BSZ;
            #pragma unroll
            for (int i = 0; i < 2; i++) {
                const int f  = tid + (i << 8);
                const int m  = f >> 2;
                const int kq = (f & 3) << 2;
                Asn[m * APAD + kq + 0] = f2tf32(av[i].x);
                Asn[m * APAD + kq + 1] = f2tf32(av[i].y);
                Asn[m * APAD + kq + 2] = f2tf32(av[i].z);
                Asn[m * APAD + kq + 3] = f2tf32(av[i].w);
                const int kk = f >> 5;
                const int n  = (f & 31) << 2;
                Bsn[kk * BPAD + n + 0] = f2tf32(bv[i].x);
                Bsn[kk * BPAD + n + 1] = f2tf32(bv[i].y);
                Bsn[kk * BPAD + n + 2] = f2tf32(bv[i].z);
                Bsn[kk * BPAD + n + 3] = f2tf32(bv[i].w);
            }
        }
        __syncthreads();
    }

    #pragma unroll
    for (int mt = 0; mt < 4; mt++) {
        const int r = bm + mrow + mt * 16 + g;
        #pragma unroll
        for (int nt = 0; nt < 4; nt++) {
            const int c = bn + nb + nt * 8 + 2 * t4;
            const float b0 = bias[c], b1 = bias[c + 1];
            float v0 = acc[mt][nt][0] + b0;
            float v1 = acc[mt][nt][1] + b1;
            float v2 = acc[mt][nt][2] + b0;
            float v3 = acc[mt][nt][3] + b1;
            if (relu) {
                v0 = fmaxf(v0, 0.f); v1 = fmaxf(v1, 0.f);
                v2 = fmaxf(v2, 0.f); v3 = fmaxf(v3, 0.f);
            }
            *(float2*)&C[(size_t)r * N + c]       = make_float2(v0, v1);
            *(float2*)&C[(size_t)(r + 8) * N + c] = make_float2(v2, v3);
        }
    }
}

// ---------------------------------------------------------------------------
// Tensor-core flash attention v2: q-tile 128, warp owns 16 rows x ALL 64 kv.
// Softmax entirely in registers (quad shuffles); P relayout via warp-private
// smem rows (syncwarp only). Block syncs: 2 per kv tile (K/V load).
// Dynamic smem: Ss[128][68] + Ks[64][36] + Vs[64][40] = 54272 B.
// ---------------------------------------------------------------------------
constexpr int SS_STR = 68;
constexpr int KS_STR = 36;
constexpr int VS_STR = 40;
constexpr int SS_OFF = 0;
constexpr int KS_OFF = 128 * SS_STR;            // 8704
constexpr int VS_OFF = KS_OFF + 64 * KS_STR;    // 11008
constexpr int ATTN_SMEM_BYTES = (VS_OFF + 64 * VS_STR) * 4;  // 54272

__global__ __launch_bounds__(256) void attn_tc(
    const float* __restrict__ QK, const float* __restrict__ Vp,
    float* __restrict__ O, int strict)
{
    extern __shared__ float sm[];
    float* Ssm = sm + SS_OFF;
    float* Ksm = sm + KS_OFF;
    float* Vsm = sm + VS_OFF;

    const int qt = blockIdx.x;          // 0..3
    const int bh = blockIdx.y;          // 0..511
    const int b  = bh >> 3;
    const int h  = bh & 7;
    const int q0 = qt << 7;
    const int t    = threadIdx.x;
    const int lane = t & 31;
    const int warp = t >> 5;
    const int m0   = warp << 4;         // warp's 16 rows
    const int g    = lane >> 2;
    const int t4   = lane & 3;

    const size_t base = (size_t)(b * S_) * D_ + h * DK_;

    // ---- stage Q (128 x 32) into Ssm, then extract per-warp Q fragments
    for (int i = t; i < 1024; i += 256) {
        const int r = i >> 3, c = (i & 7) << 2;
        float4 v = *(const float4*)&QK[base + (size_t)(q0 + r) * D_ + c];
        Ssm[r * SS_STR + c + 0] = f2tf32(v.x);
        Ssm[r * SS_STR + c + 1] = f2tf32(v.y);
        Ssm[r * SS_STR + c + 2] = f2tf32(v.z);
        Ssm[r * SS_STR + c + 3] = f2tf32(v.w);
    }
    __syncthreads();
    unsigned qf[4][4];
    #pragma unroll
    for (int ks = 0; ks < 4; ks++) {
        const int k = ks * 8;
        qf[ks][0] = __float_as_uint(Ssm[(m0 + g) * SS_STR + k + t4]);
        qf[ks][1] = __float_as_uint(Ssm[(m0 + g + 8) * SS_STR + k + t4]);
        qf[ks][2] = __float_as_uint(Ssm[(m0 + g) * SS_STR + k + t4 + 4]);
        qf[ks][3] = __float_as_uint(Ssm[(m0 + g + 8) * SS_STR + k + t4 + 4]);
    }
    // (first loop __syncthreads protects Ssm reuse as P-buffer)

    float acc_o[4][4];
    #pragma unroll
    for (int nt = 0; nt < 4; nt++)
        #pragma unroll
        for (int i = 0; i < 4; i++) acc_o[nt][i] = 0.f;
    float mrow[2] = { -1e30f, -1e30f };
    float lrow[2] = { 0.f, 0.f };

    const int rg  = q0 + m0 + g - strict;   // allowed: col <= rg
    const int rg8 = rg + 8;
    const int ktmax = 2 * qt + 1;

    for (int kt = 0; kt <= ktmax; kt++) {
        const int k0 = kt << 6;
        __syncthreads();    // prev iter's K/V reads done (and Q extract, iter 0)
        for (int i = t; i < 512; i += 256) {
            const int rr = i >> 3, c = (i & 7) << 2;
            float4 kv = *(const float4*)&QK[base + (size_t)(k0 + rr) * D_ + c];
            Ksm[rr * KS_STR + c + 0] = f2tf32(kv.x);
            Ksm[rr * KS_STR + c + 1] = f2tf32(kv.y);
            Ksm[rr * KS_STR + c + 2] = f2tf32(kv.z);
            Ksm[rr * KS_STR + c + 3] = f2tf32(kv.w);
            float4 vv = *(const float4*)&Vp[base + (size_t)(k0 + rr) * D_ + c];
            Vsm[rr * VS_STR + c + 0] = f2tf32(vv.x);
            Vsm[rr * VS_STR + c + 1] = f2tf32(vv.y);
            Vsm[rr * VS_STR + c + 2] = f2tf32(vv.z);
            Vsm[rr * VS_STR + c + 3] = f2tf32(vv.w);
        }
        __syncthreads();

        // ---- scores: warp tile 16 x 64
        float s[8][4];
        #pragma unroll
        for (int nt = 0; nt < 8; nt++)
            #pragma unroll
            for (int i = 0; i < 4; i++) s[nt][i] = 0.f;
        #pragma unroll
        for (int ks = 0; ks < 4; ks++) {
            const int kb = ks * 8;
            #pragma unroll
            for (int nt = 0; nt < 8; nt++) {
                const float* Kp = &Ksm[(nt * 8 + g) * KS_STR + kb + t4];
                unsigned b0 = __float_as_uint(Kp[0]);
                unsigned b1 = __float_as_uint(Kp[4]);
                mma_tf32(s[nt][0], s[nt][1], s[nt][2], s[nt][3],
                         qf[ks][0], qf[ks][1], qf[ks][2], qf[ks][3], b0, b1);
            }
        }

        // ---- mask + scale (register)
        #pragma unroll
        for (int nt = 0; nt < 8; nt++) {
            const int c0c = k0 + nt * 8 + 2 * t4;
            const int c1c = c0c + 1;
            s[nt][0] = (c0c <= rg ) ? s[nt][0] * SCALE_ : -1e30f;
            s[nt][1] = (c1c <= rg ) ? s[nt][1] * SCALE_ : -1e30f;
            s[nt][2] = (c0c <= rg8) ? s[nt][2] * SCALE_ : -1e30f;
            s[nt][3] = (c1c <= rg8) ? s[nt][3] * SCALE_ : -1e30f;
        }

        // ---- row max (register + quad shuffle)
        float mx0 = -1e30f, mx1 = -1e30f;
        #pragma unroll
        for (int nt = 0; nt < 8; nt++) {
            mx0 = fmaxf(mx0, fmaxf(s[nt][0], s[nt][1]));
            mx1 = fmaxf(mx1, fmaxf(s[nt][2], s[nt][3]));
        }
        mx0 = fmaxf(mx0, __shfl_xor_sync(0xffffffffu, mx0, 1));
        mx0 = fmaxf(mx0, __shfl_xor_sync(0xffffffffu, mx0, 2));
        mx1 = fmaxf(mx1, __shfl_xor_sync(0xffffffffu, mx1, 1));
        mx1 = fmaxf(mx1, __shfl_xor_sync(0xffffffffu, mx1, 2));
        const float nm0 = fmaxf(mrow[0], mx0);
        const float nm1 = fmaxf(mrow[1], mx1);
        const float cr0 = __expf(mrow[0] - nm0);
        const float cr1 = __expf(mrow[1] - nm1);

        // ---- exp + P store to warp-private smem rows
        float ps0 = 0.f, ps1 = 0.f;
        #pragma unroll
        for (int nt = 0; nt < 8; nt++) {
            const float p0 = (s[nt][0] > -1e29f) ? f2tf32(__expf(s[nt][0] - nm0)) : 0.f;
            const float p1 = (s[nt][1] > -1e29f) ? f2tf32(__expf(s[nt][1] - nm0)) : 0.f;
            const float p2 = (s[nt][2] > -1e29f) ? f2tf32(__expf(s[nt][2] - nm1)) : 0.f;
            const float p3 = (s[nt][3] > -1e29f) ? f2tf32(__expf(s[nt][3] - nm1)) : 0.f;
            ps0 += p0 + p1;
            ps1 += p2 + p3;
            const int cl = nt * 8 + 2 * t4;
            *(float2*)&Ssm[(m0 + g) * SS_STR + cl]     = make_float2(p0, p1);
            *(float2*)&Ssm[(m0 + g + 8) * SS_STR + cl] = make_float2(p2, p3);
        }
        ps0 += __shfl_xor_sync(0xffffffffu, ps0, 1);
        ps0 += __shfl_xor_sync(0xffffffffu, ps0, 2);
        ps1 += __shfl_xor_sync(0xffffffffu, ps1, 1);
        ps1 += __shfl_xor_sync(0xffffffffu, ps1, 2);
        lrow[0] = lrow[0] * cr0 + ps0;
        lrow[1] = lrow[1] * cr1 + ps1;
        mrow[0] = nm0;
        mrow[1] = nm1;
        __syncwarp();

        // ---- rescale accumulators, then PV (warp tile 16 x 32)
        #pragma unroll
        for (int nt = 0; nt < 4; nt++) {
            acc_o[nt][0] *= cr0; acc_o[nt][1] *= cr0;
            acc_o[nt][2] *= cr1; acc_o[nt][3] *= cr1;
        }
        #pragma unroll
        for (int kk = 0; kk < 8; kk++) {
            const int kb = kk * 8;
            unsigned a0 = __float_as_uint(Ssm[(m0 + g) * SS_STR + kb + t4]);
            unsigned a1 = __float_as_uint(Ssm[(m0 + g + 8) * SS_STR + kb + t4]);
            unsigned a2 = __float_as_uint(Ssm[(m0 + g) * SS_STR + kb + t4 + 4]);
            unsigned a3 = __float_as_uint(Ssm[(m0 + g + 8) * SS_STR + kb + t4 + 4]);
            #pragma unroll
            for (int nt = 0; nt < 4; nt++) {
                const float* Vpp = &Vsm[(kb + t4) * VS_STR + nt * 8 + g];
                unsigned b0 = __float_as_uint(Vpp[0]);
                unsigned b1 = __float_as_uint(Vpp[4 * VS_STR]);
                mma_tf32(acc_o[nt][0], acc_o[nt][1], acc_o[nt][2], acc_o[nt][3],
                         a0, a1, a2, a3, b0, b1);
            }
        }
    }

    // ---- finalize: divide by l (fully-masked row -> 0), write out
    const float i0 = (lrow[0] > 0.f) ? 1.f / lrow[0] : 0.f;
    const float i1 = (lrow[1] > 0.f) ? 1.f / lrow[1] : 0.f;
    const int row = q0 + m0 + g;
    #pragma unroll
    for (int nt = 0; nt < 4; nt++) {
        const int c = nt * 8 + 2 * t4;
        *(float2*)&O[base + (size_t)row * D_ + c] =
            make_float2(acc_o[nt][0] * i0, acc_o[nt][1] * i0);
        *(float2*)&O[base + (size_t)(row + 8) * D_ + c] =
            make_float2(acc_o[nt][2] * i1, acc_o[nt][3] * i1);
    }
}

// ---------------------------------------------------------------------------
// Fused residual add + LayerNorm: warp-per-row (256 floats, 8 per lane).
// ---------------------------------------------------------------------------
__global__ __launch_bounds__(256) void add_ln_kernel(
    const float* __restrict__ X, const float* __restrict__ R,
    const float* __restrict__ gam, const float* __restrict__ bet,
    float* __restrict__ O)
{
    const int warp = threadIdx.x >> 5;
    const int lane = threadIdx.x & 31;
    const int row  = blockIdx.x * 8 + warp;
    const size_t off = (size_t)row * D_ + lane * 8;

    float4 x0 = *(const float4*)&X[off];
    float4 x1 = *(const float4*)&X[off + 4];
    float4 r0 = *(const float4*)&R[off];
    float4 r1 = *(const float4*)&R[off + 4];
    float v[8] = { x0.x + r0.x, x0.y + r0.y, x0.z + r0.z, x0.w + r0.w,
                   x1.x + r1.x, x1.y + r1.y, x1.z + r1.z, x1.w + r1.w };

    float s = 0.f;
    #pragma unroll
    for (int i = 0; i < 8; i++) s += v[i];
    #pragma unroll
    for (int o = 16; o > 0; o >>= 1) s += __shfl_xor_sync(0xffffffffu, s, o);
    const float mu = s * (1.f / 256.f);

    float s2 = 0.f;
    #pragma unroll
    for (int i = 0; i < 8; i++) { v[i] -= mu; s2 += v[i] * v[i]; }
    #pragma unroll
    for (int o = 16; o > 0; o >>= 1) s2 += __shfl_xor_sync(0xffffffffu, s2, o);
    const float rs = rsqrtf(s2 * (1.f / 256.f) + 1e-5f);

    const int c = lane * 8;
    float4 ga = *(const float4*)&gam[c];
    float4 gb = *(const float4*)&gam[c + 4];
    float4 ba = *(const float4*)&bet[c];
    float4 bb = *(const float4*)&bet[c + 4];

    float4 oa = make_float4(v[0] * rs * ga.x + ba.x, v[1] * rs * ga.y + ba.y,
                            v[2] * rs * ga.z + ba.z, v[3] * rs * ga.w + ba.w);
    float4 ob = make_float4(v[4] * rs * gb.x + bb.x, v[5] * rs * gb.y + bb.y,
                            v[6] * rs * gb.z + bb.z, v[7] * rs * gb.w + bb.w);
    *(float4*)&O[off]     = oa;
    *(float4*)&O[off + 4] = ob;
}

// ---------------------------------------------------------------------------
// Host-side orchestration
// ---------------------------------------------------------------------------
struct Scratch { float *y, *x, *kp, *vp, *att, *o, *x1, *f, *h; };

static void launch_layer(const float* Qin, const float* Vin, float* Out,
                         int li, int strict, int apply_pos,
                         void* const* d_in, const Scratch& P)
{
    const float* Wk  = (const float*)d_in[2]  + (size_t)li * D_ * D_;
    const float* bk  = (const float*)d_in[3]  + (size_t)li * D_;
    const float* Wv  = (const float*)d_in[4]  + (size_t)li * D_ * D_;
    const float* bv  = (const float*)d_in[5]  + (size_t)li * D_;
    const float* Wo  = (const float*)d_in[6]  + (size_t)li * D_ * D_;
    const float* bo  = (const float*)d_in[7]  + (size_t)li * D_;
    const float* g1  = (const float*)d_in[8]  + (size_t)li * D_;
    const float* be1 = (const float*)d_in[9]  + (size_t)li * D_;
    const float* W1  = (const float*)d_in[10] + (size_t)li * D_ * DFF_;
    const float* bf1 = (const float*)d_in[11] + (size_t)li * DFF_;
    const float* W2  = (const float*)d_in[12] + (size_t)li * DFF_ * D_;
    const float* bf2 = (const float*)d_in[13] + (size_t)li * D_;
    const float* g2  = (const float*)d_in[14] + (size_t)li * D_;
    const float* be2 = (const float*)d_in[15] + (size_t)li * D_;

    const dim3 gp(D_ / 128, BS_ / 128);   // (2, 256)

    // q==k projection (kq_same): one GEMM serves both
    gemm_tc<<<gp, 256>>>(Qin, Wk, bk, P.kp, BS_, D_, D_, 0);
    gemm_tc<<<gp, 256>>>(Vin, Wv, bv, P.vp, BS_, D_, D_, 0);
    attn_tc<<<dim3(S_ / 128, B_ * H_), 256, ATTN_SMEM_BYTES>>>(P.kp, P.vp, P.att, strict);
    gemm_tc<<<gp, 256>>>(P.att, Wo, bo, P.o, BS_, D_, D_, 0);

    float* ln1out = apply_pos ? P.x1 : Out;
    add_ln_kernel<<<BS_ / 8, 256>>>(Qin, P.o, g1, be1, ln1out);

    if (apply_pos) {
        gemm_tc<<<dim3(DFF_ / 128, BS_ / 128), 256>>>(P.x1, W1, bf1, P.h, BS_, DFF_, D_, 1);
        gemm_tc<<<dim3(D_ / 128, BS_ / 128), 256>>>(P.h, W2, bf2, P.f, BS_, D_, DFF_, 0);
        add_ln_kernel<<<BS_ / 8, 256>>>(P.x1, P.f, g2, be2, Out);
    }
}

extern "C" void kernel_launch(void* const* d_in, const int* in_sizes, int n_in,
                              void* d_out, int out_size)
{
    (void)in_sizes; (void)n_in; (void)out_size;
    const float* qe = (const float*)d_in[0];   // q_embed_data  -> x stream
    const float* qa = (const float*)d_in[1];   // qa_embed_data -> y stream

    // allow >48KB dynamic smem for attention (host attribute; not a graph node)
    static bool attr_done = false;
    if (!attr_done) {
        cudaFuncSetAttribute(attn_tc, cudaFuncAttributeMaxDynamicSharedMemorySize,
                             ATTN_SMEM_BYTES);
        attr_done = true;
    }

    Scratch P;
    cudaGetSymbolAddress((void**)&P.y,  g_y);
    cudaGetSymbolAddress((void**)&P.x,  g_x);
    cudaGetSymbolAddress((void**)&P.kp, g_kp);
    cudaGetSymbolAddress((void**)&P.vp, g_vp);
    cudaGetSymbolAddress((void**)&P.att, g_att);
    cudaGetSymbolAddress((void**)&P.o,  g_o);
    cudaGetSymbolAddress((void**)&P.x1, g_x1);
    cudaGetSymbolAddress((void**)&P.f,  g_f);
    cudaGetSymbolAddress((void**)&P.h,  g_h);

    // Encoder blocks (y = qa stream), mask incl. diagonal, with FFN
    launch_layer(qa,  qa,  P.y, 0, /*strict=*/0, /*apply_pos=*/1, d_in, P);
    launch_layer(P.y, P.y, P.y, 1, 0, 1, d_in, P);

    // Decoder blocks on x stream
    launch_layer(qe,  qe,  P.x, 2, /*strict=*/0, /*apply_pos=*/0, d_in, P);   // self, no FFN
    launch_layer(P.x, P.y, P.x, 3, /*strict=*/1, /*apply_pos=*/1, d_in, P);   // cross (V=y)
    launch_layer(P.x, P.x, P.x, 4, 0, 0, d_in, P);                            // self, no FFN
    launch_layer(P.x, P.y, (float*)d_out, 5, 1, 1, d_in, P);                  // cross -> out
}